// round 13
// baseline (speedup 1.0000x reference)
#include <cuda_runtime.h>
#include <math.h>

#define NN 50000
#define EE 600000
#define HH 128

// ---------------- scratch (device globals; no allocation allowed) ----------------
__device__ float g_z[(size_t)NN * HH];        // encoder output
__device__ float g_AB[2 * (size_t)NN * HH];   // A = z@Mw[0:128], B = z@Mw[128:256]
__device__ float g_agg[(size_t)NN * HH];      // segment-max aggregate
__device__ int   g_cnt[NN];
__device__ int   g_off[NN + 1];
__device__ int   g_cur[NN];
__device__ int   g_eid[EE];
__device__ float g_colpart[1024 * HH];        // per-warp column partial sums of h

// ---------------- CSR build ----------------
__global__ void zero_cnt_kernel(int* __restrict__ cnt) {
    int i = blockIdx.x * blockDim.x + threadIdx.x;
    if (i < NN) cnt[i] = 0;
}

__global__ void hist_kernel(const int* __restrict__ tgt, int* __restrict__ cnt) {
    int e = blockIdx.x * blockDim.x + threadIdx.x;
    if (e < EE) atomicAdd(&cnt[tgt[e]], 1);
}

__global__ void scan_kernel(const int* __restrict__ cnt, int* __restrict__ off,
                            int* __restrict__ cur) {
    __shared__ int sums[1024];
    int t = threadIdx.x;
    const int CH = (NN + 1023) / 1024;  // 49
    int base = t * CH;
    int s = 0;
    for (int i = 0; i < CH; ++i) {
        int idx = base + i;
        if (idx < NN) s += cnt[idx];
    }
    sums[t] = s;
    __syncthreads();
    for (int d = 1; d < 1024; d <<= 1) {
        int v = (t >= d) ? sums[t - d] : 0;
        __syncthreads();
        if (t >= d) sums[t] += v;
        __syncthreads();
    }
    int pre = (t == 0) ? 0 : sums[t - 1];
    for (int i = 0; i < CH; ++i) {
        int idx = base + i;
        if (idx < NN) {
            off[idx] = pre;
            cur[idx] = pre;
            pre += cnt[idx];
        }
    }
    if (t == 1023) off[NN] = sums[1023];
}

__global__ void scatter_kernel(const int* __restrict__ tgt, int* __restrict__ cur,
                               int* __restrict__ eid) {
    int e = blockIdx.x * blockDim.x + threadIdx.x;
    if (e < EE) {
        int p = atomicAdd(&cur[tgt[e]], 1);
        eid[p] = e;
    }
}

// ---------------- fused SGEMM:  C[M,128] = act(IN[M,K] @ W[K,128] (+ epi)) ----------------
// EPI: 0 = raw store, 1 = relu(acc + bias), 2 = relu(acc + x[row]*xw[col] + bias)  (encoder)
// TWO: input is concat [in0 | in1], each [M,128] row-major (K must be 256)
#define BM 128
#define BN 128
#define BK 16

template <int KTILES, bool TWO, int EPI>
__global__ void __launch_bounds__(256)
gemm_kernel(const float* __restrict__ in0, const float* __restrict__ in1,
            const float* __restrict__ W, const float* __restrict__ bias,
            const float* __restrict__ xcol, const float* __restrict__ xw,
            float* __restrict__ C, int wstride, size_t cstride) {
    __shared__ float As[BK][BM];
    __shared__ float Bs[BK][BN];

    const int t  = threadIdx.x;
    const int tx = t & 15;
    const int ty = t >> 4;
    const int m0 = blockIdx.x * BM;
    const float* Wp = W + (size_t)blockIdx.y * wstride;
    float*       Cp = C + (size_t)blockIdx.y * cstride;

    const int lr = t >> 2;         // 0..63
    const int lk = (t & 3) * 4;    // 0,4,8,12

    unsigned long long acc2[8][4];
#pragma unroll
    for (int i = 0; i < 8; ++i)
#pragma unroll
        for (int jp = 0; jp < 4; ++jp) acc2[i][jp] = 0ull;

#pragma unroll 1
    for (int kt = 0; kt < KTILES; ++kt) {
        const int k0 = kt * BK;
        const float* srcA = (!TWO || k0 < 128) ? in0 : in1;
        const int kk = TWO ? (k0 & 127) : k0;

        // ---- load input tile (transposed into As[k][m]) ----
#pragma unroll
        for (int p = 0; p < 2; ++p) {
            int r  = lr + p * 64;
            int gr = m0 + r;
            float4 v = make_float4(0.f, 0.f, 0.f, 0.f);
            if (gr < NN) v = *(const float4*)(srcA + (size_t)gr * 128 + kk + lk);
            As[lk + 0][r] = v.x;
            As[lk + 1][r] = v.y;
            As[lk + 2][r] = v.z;
            As[lk + 3][r] = v.w;
        }
        // ---- load weight tile (row-major, coalesced) ----
#pragma unroll
        for (int p = 0; p < 2; ++p) {
            int off = t * 4 + p * 1024;
            int kr = off >> 7, col = off & 127;
            *(float4*)&Bs[kr][col] = *(const float4*)(Wp + (size_t)(k0 + kr) * 128 + col);
        }
        __syncthreads();

#pragma unroll
        for (int k = 0; k < BK; ++k) {
            float4 a0 = *(const float4*)&As[k][ty * 8];
            float4 a1 = *(const float4*)&As[k][ty * 8 + 4];
            unsigned long long b2[4];
#pragma unroll
            for (int jp = 0; jp < 4; ++jp)
                b2[jp] = *(const unsigned long long*)&Bs[k][tx * 8 + jp * 2];
            float av[8] = {a0.x, a0.y, a0.z, a0.w, a1.x, a1.y, a1.z, a1.w};
#pragma unroll
            for (int i = 0; i < 8; ++i) {
                unsigned long long a2;
                asm("mov.b64 %0, {%1, %2};" : "=l"(a2) : "f"(av[i]), "f"(av[i]));
#pragma unroll
                for (int jp = 0; jp < 4; ++jp)
                    asm("fma.rn.f32x2 %0, %1, %2, %0;"
                        : "+l"(acc2[i][jp])
                        : "l"(a2), "l"(b2[jp]));
            }
        }
        __syncthreads();
    }

    // ---- epilogue ----
    float bcol[8], xwc[8];
    if (EPI >= 1) {
#pragma unroll
        for (int j = 0; j < 8; ++j) bcol[j] = bias[tx * 8 + j];
    }
    if (EPI == 2) {
#pragma unroll
        for (int j = 0; j < 8; ++j) xwc[j] = xw[tx * 8 + j];
    }
#pragma unroll
    for (int i = 0; i < 8; ++i) {
        int gr = m0 + ty * 8 + i;
        if (gr < NN) {
            float row[8];
#pragma unroll
            for (int jp = 0; jp < 4; ++jp)
                asm("mov.b64 {%0, %1}, %2;"
                    : "=f"(row[jp * 2]), "=f"(row[jp * 2 + 1])
                    : "l"(acc2[i][jp]));
            if (EPI == 1) {
#pragma unroll
                for (int j = 0; j < 8; ++j) row[j] = fmaxf(row[j] + bcol[j], 0.f);
            } else if (EPI == 2) {
                float xv = xcol[gr];
#pragma unroll
                for (int j = 0; j < 8; ++j)
                    row[j] = fmaxf(row[j] + xv * xwc[j] + bcol[j], 0.f);
            }
            *(float4*)(Cp + (size_t)gr * 128 + tx * 8)     = make_float4(row[0], row[1], row[2], row[3]);
            *(float4*)(Cp + (size_t)gr * 128 + tx * 8 + 4) = make_float4(row[4], row[5], row[6], row[7]);
        }
    }
}

// ---------------- per-node segment-max over edges (warp per node) ----------------
// agg[n] = max(0, max_{e: tgt(e)=n} (A[n] + B[src(e)] + ea[e]*we + mb))
// (relu folds into the max against the 0 init)
__global__ void agg_kernel(const float* __restrict__ gA, const float* __restrict__ gB,
                           const float* __restrict__ we, const float* __restrict__ mb,
                           const int* __restrict__ src, const float* __restrict__ ea,
                           const int* __restrict__ off, const int* __restrict__ eid,
                           float* __restrict__ agg) {
    int w = (blockIdx.x * blockDim.x + threadIdx.x) >> 5;
    if (w >= NN) return;
    int lane = threadIdx.x & 31;
    int c = lane << 2;
    float4 a  = *(const float4*)(gA + (size_t)w * 128 + c);
    float4 wv = *(const float4*)(we + c);
    float4 bv = *(const float4*)(mb + c);
    float bx = a.x + bv.x, by = a.y + bv.y, bz = a.z + bv.z, bw = a.w + bv.w;
    float4 acc = make_float4(0.f, 0.f, 0.f, 0.f);
    int e0 = off[w], e1 = off[w + 1];
    for (int i = e0; i < e1; ++i) {
        int e   = __ldg(eid + i);
        int s   = __ldg(src + e);
        float t = __ldg(ea + e);
        float4 b = *(const float4*)(gB + (size_t)s * 128 + c);
        acc.x = fmaxf(acc.x, fmaf(t, wv.x, bx + b.x));
        acc.y = fmaxf(acc.y, fmaf(t, wv.y, by + b.y));
        acc.z = fmaxf(acc.z, fmaf(t, wv.z, bz + b.z));
        acc.w = fmaxf(acc.w, fmaf(t, wv.w, bw + b.w));
    }
    *(float4*)(agg + (size_t)w * 128 + c) = acc;
}

// ---------------- decoder y + column partial sums of h (1024 warps) ----------------
__global__ void y_colsum_kernel(const float* __restrict__ z, const float* __restrict__ h,
                                const float* __restrict__ dw, const float* __restrict__ db,
                                float* __restrict__ y, float* __restrict__ colpart) {
    int gw = (blockIdx.x * blockDim.x + threadIdx.x) >> 5;  // 0..1023
    int lane = threadIdx.x & 31;
    int c = lane << 2;
    float4 d0 = *(const float4*)(dw + c);
    float4 d1 = *(const float4*)(dw + 128 + c);
    float dbv = db[0];
    float4 cs = make_float4(0.f, 0.f, 0.f, 0.f);
    for (int n = gw; n < NN; n += 1024) {
        float4 zz = *(const float4*)(z + (size_t)n * 128 + c);
        float4 hh = *(const float4*)(h + (size_t)n * 128 + c);
        cs.x += hh.x; cs.y += hh.y; cs.z += hh.z; cs.w += hh.w;
        float d = zz.x * d0.x + zz.y * d0.y + zz.z * d0.z + zz.w * d0.w +
                  hh.x * d1.x + hh.y * d1.y + hh.z * d1.z + hh.w * d1.w;
#pragma unroll
        for (int o = 16; o; o >>= 1) d += __shfl_xor_sync(0xffffffffu, d, o);
        if (lane == 0) y[n] = 1.0f / (1.0f + expf(-(d + dbv)));
    }
    *(float4*)(colpart + (size_t)gw * 128 + c) = cs;
}

// ---------------- terminator: ter = colmean(h)·(tw0+tw1) + tb ----------------
__global__ void ter_kernel(const float* __restrict__ colpart,
                           const float* __restrict__ tw, const float* __restrict__ tb,
                           float* __restrict__ out) {
    __shared__ float sm[1024];
    int t = threadIdx.x;        // 0..1023
    int j = t & 127, g = t >> 7;
    float s = 0.f;
#pragma unroll 8
    for (int w = g * 128; w < g * 128 + 128; ++w) s += colpart[(size_t)w * 128 + j];
    sm[t] = s;
    __syncthreads();
    if (t < 128) {
        float tot = 0.f;
#pragma unroll
        for (int gg = 0; gg < 8; ++gg) tot += sm[j + gg * 128];
        sm[t] = (tot / (float)NN) * (tw[j] + tw[128 + j]);
    }
    for (int dd = 64; dd >= 1; dd >>= 1) {
        __syncthreads();
        if (t < dd) sm[t] += sm[t + dd];
    }
    if (t == 0) out[0] = sm[0] + tb[0];
}

// ---------------- launch ----------------
extern "C" void kernel_launch(void* const* d_in, const int* in_sizes, int n_in,
                              void* d_out, int out_size) {
    const float* x     = (const float*)d_in[0];
    const float* pre_h = (const float*)d_in[1];
    const float* ea    = (const float*)d_in[2];
    const float* enc_w = (const float*)d_in[3];   // [129,128]
    const float* enc_b = (const float*)d_in[4];
    const float* M_w   = (const float*)d_in[5];   // [257,128]
    const float* M_b   = (const float*)d_in[6];
    const float* U_w   = (const float*)d_in[7];   // [256,128]
    const float* U_b   = (const float*)d_in[8];
    const float* dec_w = (const float*)d_in[9];   // [256]
    const float* dec_b = (const float*)d_in[10];
    const float* ter_w = (const float*)d_in[11];  // [256]
    const float* ter_b = (const float*)d_in[12];
    const int*   eidx  = (const int*)d_in[13];    // [2,E]
    const int* src = eidx;
    const int* tgt = eidx + EE;

    float* out    = (float*)d_out;
    float* h_out  = out;                              // [N,128]
    float* y_out  = out + (size_t)NN * HH;            // [N]
    float* ter_out = y_out + NN;                      // [1]

    float *zp, *abp, *aggp, *cpp;
    int *cntp, *offp, *curp, *eidp;
    cudaGetSymbolAddress((void**)&zp,   g_z);
    cudaGetSymbolAddress((void**)&abp,  g_AB);
    cudaGetSymbolAddress((void**)&aggp, g_agg);
    cudaGetSymbolAddress((void**)&cntp, g_cnt);
    cudaGetSymbolAddress((void**)&offp, g_off);
    cudaGetSymbolAddress((void**)&curp, g_cur);
    cudaGetSymbolAddress((void**)&eidp, g_eid);
    cudaGetSymbolAddress((void**)&cpp,  g_colpart);

    // CSR build (order-independent max => deterministic result)
    zero_cnt_kernel<<<(NN + 255) / 256, 256>>>(cntp);
    hist_kernel<<<(EE + 255) / 256, 256>>>(tgt, cntp);
    scan_kernel<<<1, 1024>>>(cntp, offp, curp);
    scatter_kernel<<<(EE + 255) / 256, 256>>>(tgt, curp, eidp);

    const int GX = (NN + BM - 1) / BM;  // 391

    // encoder: z = relu(pre_h @ enc_w[1:129] + x*enc_w[0] + enc_b)
    gemm_kernel<8, false, 2><<<dim3(GX, 1), 256>>>(
        pre_h, nullptr, enc_w + 128, enc_b, x, enc_w, zp, 0, 0);

    // A = z @ M_w[0:128], B = z @ M_w[128:256]   (grid.y selects weight/output half)
    gemm_kernel<8, false, 0><<<dim3(GX, 2), 256>>>(
        zp, nullptr, M_w, nullptr, nullptr, nullptr, abp,
        128 * 128, (size_t)NN * HH);

    // segment max
    agg_kernel<<<(NN * 32 + 255) / 256, 256>>>(
        abp, abp + (size_t)NN * HH, M_w + 256 * 128, M_b, src, ea, offp, eidp, aggp);

    // h = relu([z, agg] @ U_w + U_b)  -> directly into d_out
    gemm_kernel<16, true, 1><<<dim3(GX, 1), 256>>>(
        zp, aggp, U_w, U_b, nullptr, nullptr, h_out, 0, 0);

    // y = sigmoid([z,h] @ dec_w + dec_b); column partial sums of h
    y_colsum_kernel<<<128, 256>>>(zp, h_out, dec_w, dec_b, y_out, cpp);

    // ter scalar
    ter_kernel<<<1, 1024>>>(cpp, ter_w, ter_b, ter_out);
}

// round 14
// speedup vs baseline: 1.0031x; 1.0031x over previous
#include <cuda_runtime.h>
#include <math.h>

#define NN 50000
#define EE 600000
#define HH 128

// ---------------- scratch (device globals; no allocation allowed) ----------------
__device__ float g_z[(size_t)NN * HH];        // encoder output
__device__ float g_AB[2 * (size_t)NN * HH];   // A = z@Mw[0:128], B = z@Mw[128:256]
__device__ float g_agg[(size_t)NN * HH];      // segment-max aggregate
__device__ int   g_cnt[NN];
__device__ int   g_off[NN + 1];
__device__ int   g_cur[NN];
__device__ int   g_eid[EE];
__device__ float g_colpart[1024 * HH];        // per-warp column partial sums of h

// ---------------- CSR build ----------------
__global__ void zero_cnt_kernel(int* __restrict__ cnt) {
    int i = blockIdx.x * blockDim.x + threadIdx.x;
    if (i < NN) cnt[i] = 0;
}

__global__ void hist_kernel(const int* __restrict__ tgt, int* __restrict__ cnt) {
    int e = blockIdx.x * blockDim.x + threadIdx.x;
    if (e < EE) atomicAdd(&cnt[tgt[e]], 1);
}

__global__ void scan_kernel(const int* __restrict__ cnt, int* __restrict__ off,
                            int* __restrict__ cur) {
    __shared__ int sums[1024];
    int t = threadIdx.x;
    const int CH = (NN + 1023) / 1024;  // 49
    int base = t * CH;
    int s = 0;
    for (int i = 0; i < CH; ++i) {
        int idx = base + i;
        if (idx < NN) s += cnt[idx];
    }
    sums[t] = s;
    __syncthreads();
    for (int d = 1; d < 1024; d <<= 1) {
        int v = (t >= d) ? sums[t - d] : 0;
        __syncthreads();
        if (t >= d) sums[t] += v;
        __syncthreads();
    }
    int pre = (t == 0) ? 0 : sums[t - 1];
    for (int i = 0; i < CH; ++i) {
        int idx = base + i;
        if (idx < NN) {
            off[idx] = pre;
            cur[idx] = pre;
            pre += cnt[idx];
        }
    }
    if (t == 1023) off[NN] = sums[1023];
}

__global__ void scatter_kernel(const int* __restrict__ tgt, int* __restrict__ cur,
                               int* __restrict__ eid) {
    int e = blockIdx.x * blockDim.x + threadIdx.x;
    if (e < EE) {
        int p = atomicAdd(&cur[tgt[e]], 1);
        eid[p] = e;
    }
}

// ---------------- fused SGEMM:  C[M,128] = act(IN[M,K] @ W[K,128] (+ epi)) ----------------
// EPI: 0 = raw store, 1 = relu(acc + bias), 2 = relu(acc + x[row]*xw[col] + bias)  (encoder)
// TWO: input is concat [in0 | in1], each [M,128] row-major (K must be 256)
#define BM 128
#define BN 128
#define BK 16

template <int KTILES, bool TWO, int EPI>
__global__ void __launch_bounds__(256)
gemm_kernel(const float* __restrict__ in0, const float* __restrict__ in1,
            const float* __restrict__ W, const float* __restrict__ bias,
            const float* __restrict__ xcol, const float* __restrict__ xw,
            float* __restrict__ C, int wstride, size_t cstride) {
    __shared__ float As[BK][BM];
    __shared__ float Bs[BK][BN];

    const int t  = threadIdx.x;
    const int tx = t & 15;
    const int ty = t >> 4;
    const int m0 = blockIdx.x * BM;
    const float* Wp = W + (size_t)blockIdx.y * wstride;
    float*       Cp = C + (size_t)blockIdx.y * cstride;

    const int lr = t >> 2;         // 0..63
    const int lk = (t & 3) * 4;    // 0,4,8,12

    unsigned long long acc2[8][4];
#pragma unroll
    for (int i = 0; i < 8; ++i)
#pragma unroll
        for (int jp = 0; jp < 4; ++jp) acc2[i][jp] = 0ull;

#pragma unroll 1
    for (int kt = 0; kt < KTILES; ++kt) {
        const int k0 = kt * BK;
        const float* srcA = (!TWO || k0 < 128) ? in0 : in1;
        const int kk = TWO ? (k0 & 127) : k0;

        // ---- load input tile (transposed into As[k][m]) ----
#pragma unroll
        for (int p = 0; p < 2; ++p) {
            int r  = lr + p * 64;
            int gr = m0 + r;
            float4 v = make_float4(0.f, 0.f, 0.f, 0.f);
            if (gr < NN) v = *(const float4*)(srcA + (size_t)gr * 128 + kk + lk);
            As[lk + 0][r] = v.x;
            As[lk + 1][r] = v.y;
            As[lk + 2][r] = v.z;
            As[lk + 3][r] = v.w;
        }
        // ---- load weight tile (row-major, coalesced) ----
#pragma unroll
        for (int p = 0; p < 2; ++p) {
            int off = t * 4 + p * 1024;
            int kr = off >> 7, col = off & 127;
            *(float4*)&Bs[kr][col] = *(const float4*)(Wp + (size_t)(k0 + kr) * 128 + col);
        }
        __syncthreads();

#pragma unroll
        for (int k = 0; k < BK; ++k) {
            float4 a0 = *(const float4*)&As[k][ty * 8];
            float4 a1 = *(const float4*)&As[k][ty * 8 + 4];
            unsigned long long b2[4];
#pragma unroll
            for (int jp = 0; jp < 4; ++jp)
                b2[jp] = *(const unsigned long long*)&Bs[k][tx * 8 + jp * 2];
            float av[8] = {a0.x, a0.y, a0.z, a0.w, a1.x, a1.y, a1.z, a1.w};
#pragma unroll
            for (int i = 0; i < 8; ++i) {
                unsigned long long a2;
                asm("mov.b64 %0, {%1, %2};" : "=l"(a2) : "f"(av[i]), "f"(av[i]));
#pragma unroll
                for (int jp = 0; jp < 4; ++jp)
                    asm("fma.rn.f32x2 %0, %1, %2, %0;"
                        : "+l"(acc2[i][jp])
                        : "l"(a2), "l"(b2[jp]));
            }
        }
        __syncthreads();
    }

    // ---- epilogue ----
    float bcol[8], xwc[8];
    if (EPI >= 1) {
#pragma unroll
        for (int j = 0; j < 8; ++j) bcol[j] = bias[tx * 8 + j];
    }
    if (EPI == 2) {
#pragma unroll
        for (int j = 0; j < 8; ++j) xwc[j] = xw[tx * 8 + j];
    }
#pragma unroll
    for (int i = 0; i < 8; ++i) {
        int gr = m0 + ty * 8 + i;
        if (gr < NN) {
            float row[8];
#pragma unroll
            for (int jp = 0; jp < 4; ++jp)
                asm("mov.b64 {%0, %1}, %2;"
                    : "=f"(row[jp * 2]), "=f"(row[jp * 2 + 1])
                    : "l"(acc2[i][jp]));
            if (EPI == 1) {
#pragma unroll
                for (int j = 0; j < 8; ++j) row[j] = fmaxf(row[j] + bcol[j], 0.f);
            } else if (EPI == 2) {
                float xv = xcol[gr];
#pragma unroll
                for (int j = 0; j < 8; ++j)
                    row[j] = fmaxf(row[j] + xv * xwc[j] + bcol[j], 0.f);
            }
            *(float4*)(Cp + (size_t)gr * 128 + tx * 8)     = make_float4(row[0], row[1], row[2], row[3]);
            *(float4*)(Cp + (size_t)gr * 128 + tx * 8 + 4) = make_float4(row[4], row[5], row[6], row[7]);
        }
    }
}

// ---------------- per-node segment-max over edges (warp per node) ----------------
// agg[n] = max(0, max_{e: tgt(e)=n} (A[n] + B[src(e)] + ea[e]*we + mb))
// (relu folds into the max against the 0 init)
__global__ void agg_kernel(const float* __restrict__ gA, const float* __restrict__ gB,
                           const float* __restrict__ we, const float* __restrict__ mb,
                           const int* __restrict__ src, const float* __restrict__ ea,
                           const int* __restrict__ off, const int* __restrict__ eid,
                           float* __restrict__ agg) {
    int w = (blockIdx.x * blockDim.x + threadIdx.x) >> 5;
    if (w >= NN) return;
    int lane = threadIdx.x & 31;
    int c = lane << 2;
    float4 a  = *(const float4*)(gA + (size_t)w * 128 + c);
    float4 wv = *(const float4*)(we + c);
    float4 bv = *(const float4*)(mb + c);
    float bx = a.x + bv.x, by = a.y + bv.y, bz = a.z + bv.z, bw = a.w + bv.w;
    float4 acc = make_float4(0.f, 0.f, 0.f, 0.f);
    int e0 = off[w], e1 = off[w + 1];
    for (int i = e0; i < e1; ++i) {
        int e   = __ldg(eid + i);
        int s   = __ldg(src + e);
        float t = __ldg(ea + e);
        float4 b = *(const float4*)(gB + (size_t)s * 128 + c);
        acc.x = fmaxf(acc.x, fmaf(t, wv.x, bx + b.x));
        acc.y = fmaxf(acc.y, fmaf(t, wv.y, by + b.y));
        acc.z = fmaxf(acc.z, fmaf(t, wv.z, bz + b.z));
        acc.w = fmaxf(acc.w, fmaf(t, wv.w, bw + b.w));
    }
    *(float4*)(agg + (size_t)w * 128 + c) = acc;
}

// ---------------- decoder y + column partial sums of h (1024 warps) ----------------
__global__ void y_colsum_kernel(const float* __restrict__ z, const float* __restrict__ h,
                                const float* __restrict__ dw, const float* __restrict__ db,
                                float* __restrict__ y, float* __restrict__ colpart) {
    int gw = (blockIdx.x * blockDim.x + threadIdx.x) >> 5;  // 0..1023
    int lane = threadIdx.x & 31;
    int c = lane << 2;
    float4 d0 = *(const float4*)(dw + c);
    float4 d1 = *(const float4*)(dw + 128 + c);
    float dbv = db[0];
    float4 cs = make_float4(0.f, 0.f, 0.f, 0.f);
    for (int n = gw; n < NN; n += 1024) {
        float4 zz = *(const float4*)(z + (size_t)n * 128 + c);
        float4 hh = *(const float4*)(h + (size_t)n * 128 + c);
        cs.x += hh.x; cs.y += hh.y; cs.z += hh.z; cs.w += hh.w;
        float d = zz.x * d0.x + zz.y * d0.y + zz.z * d0.z + zz.w * d0.w +
                  hh.x * d1.x + hh.y * d1.y + hh.z * d1.z + hh.w * d1.w;
#pragma unroll
        for (int o = 16; o; o >>= 1) d += __shfl_xor_sync(0xffffffffu, d, o);
        if (lane == 0) y[n] = 1.0f / (1.0f + expf(-(d + dbv)));
    }
    *(float4*)(colpart + (size_t)gw * 128 + c) = cs;
}

// ---------------- terminator: ter = colmean(h)·(tw0+tw1) + tb ----------------
__global__ void ter_kernel(const float* __restrict__ colpart,
                           const float* __restrict__ tw, const float* __restrict__ tb,
                           float* __restrict__ out) {
    __shared__ float sm[1024];
    int t = threadIdx.x;        // 0..1023
    int j = t & 127, g = t >> 7;
    float s = 0.f;
#pragma unroll 8
    for (int w = g * 128; w < g * 128 + 128; ++w) s += colpart[(size_t)w * 128 + j];
    sm[t] = s;
    __syncthreads();
    if (t < 128) {
        float tot = 0.f;
#pragma unroll
        for (int gg = 0; gg < 8; ++gg) tot += sm[j + gg * 128];
        sm[t] = (tot / (float)NN) * (tw[j] + tw[128 + j]);
    }
    for (int dd = 64; dd >= 1; dd >>= 1) {
        __syncthreads();
        if (t < dd) sm[t] += sm[t + dd];
    }
    if (t == 0) out[0] = sm[0] + tb[0];
}

// ---------------- launch ----------------
extern "C" void kernel_launch(void* const* d_in, const int* in_sizes, int n_in,
                              void* d_out, int out_size) {
    const float* x     = (const float*)d_in[0];
    const float* pre_h = (const float*)d_in[1];
    const float* ea    = (const float*)d_in[2];
    const float* enc_w = (const float*)d_in[3];   // [129,128]
    const float* enc_b = (const float*)d_in[4];
    const float* M_w   = (const float*)d_in[5];   // [257,128]
    const float* M_b   = (const float*)d_in[6];
    const float* U_w   = (const float*)d_in[7];   // [256,128]
    const float* U_b   = (const float*)d_in[8];
    const float* dec_w = (const float*)d_in[9];   // [256]
    const float* dec_b = (const float*)d_in[10];
    const float* ter_w = (const float*)d_in[11];  // [256]
    const float* ter_b = (const float*)d_in[12];
    const int*   eidx  = (const int*)d_in[13];    // [2,E]
    const int* src = eidx;
    const int* tgt = eidx + EE;

    float* out    = (float*)d_out;
    float* h_out  = out;                              // [N,128]
    float* y_out  = out + (size_t)NN * HH;            // [N]
    float* ter_out = y_out + NN;                      // [1]

    float *zp, *abp, *aggp, *cpp;
    int *cntp, *offp, *curp, *eidp;
    cudaGetSymbolAddress((void**)&zp,   g_z);
    cudaGetSymbolAddress((void**)&abp,  g_AB);
    cudaGetSymbolAddress((void**)&aggp, g_agg);
    cudaGetSymbolAddress((void**)&cntp, g_cnt);
    cudaGetSymbolAddress((void**)&offp, g_off);
    cudaGetSymbolAddress((void**)&curp, g_cur);
    cudaGetSymbolAddress((void**)&eidp, g_eid);
    cudaGetSymbolAddress((void**)&cpp,  g_colpart);

    // CSR build (order-independent max => deterministic result)
    zero_cnt_kernel<<<(NN + 255) / 256, 256>>>(cntp);
    hist_kernel<<<(EE + 255) / 256, 256>>>(tgt, cntp);
    scan_kernel<<<1, 1024>>>(cntp, offp, curp);
    scatter_kernel<<<(EE + 255) / 256, 256>>>(tgt, curp, eidp);

    const int GX = (NN + BM - 1) / BM;  // 391

    // encoder: z = relu(pre_h @ enc_w[1:129] + x*enc_w[0] + enc_b)
    gemm_kernel<8, false, 2><<<dim3(GX, 1), 256>>>(
        pre_h, nullptr, enc_w + 128, enc_b, x, enc_w, zp, 0, 0);

    // A = z @ M_w[0:128], B = z @ M_w[128:256]   (grid.y selects weight/output half)
    gemm_kernel<8, false, 0><<<dim3(GX, 2), 256>>>(
        zp, nullptr, M_w, nullptr, nullptr, nullptr, abp,
        128 * 128, (size_t)NN * HH);

    // segment max
    agg_kernel<<<(NN * 32 + 255) / 256, 256>>>(
        abp, abp + (size_t)NN * HH, M_w + 256 * 128, M_b, src, ea, offp, eidp, aggp);

    // h = relu([z, agg] @ U_w + U_b)  -> directly into d_out
    gemm_kernel<16, true, 1><<<dim3(GX, 1), 256>>>(
        zp, aggp, U_w, U_b, nullptr, nullptr, h_out, 0, 0);

    // y = sigmoid([z,h] @ dec_w + dec_b); column partial sums of h
    y_colsum_kernel<<<128, 256>>>(zp, h_out, dec_w, dec_b, y_out, cpp);

    // ter scalar
    ter_kernel<<<1, 1024>>>(cpp, ter_w, ter_b, ter_out);
}